// round 9
// baseline (speedup 1.0000x reference)
#include <cuda_runtime.h>

// out[to_i[j]] = mat_i[from_i[j]], 3 segments of L rows, D=64 fp32 (256B/row).
// 16 threads per row (one float4 each). Each thread handles row pair
// {2*r0, 2*r0+1} of EACH segment (compile-time segment map, no branches):
//   - 6 vectorized int2 index loads (adjacent pair -> one 8B load each)
//   - 6 independent LDG.128 gathers (MLP=6)
//   - 6 STG.128 scatters (plain caching; R6 showed .cs is neutral-to-worse)
// Measured HBM traffic is already at the compulsory minimum (~528MB), so this
// round only trims the index prologue critical path / LSU wavefronts.

#define D4 16   // D=64 floats = 16 float4

__global__ void __launch_bounds__(256)
mis_u6p_kernel(const float4* __restrict__ m0,
               const float4* __restrict__ m1,
               const float4* __restrict__ m2,
               const int2*   __restrict__ f0,   // viewed as pairs
               const int2*   __restrict__ f1,
               const int2*   __restrict__ f2,
               const int2*   __restrict__ t0,
               const int2*   __restrict__ t1,
               const int2*   __restrict__ t2,
               float4*       __restrict__ out,
               int halfL)
{
    const int tid = blockIdx.x * blockDim.x + threadIdx.x;
    const int q   = tid & (D4 - 1);
    const int p   = tid >> 4;                 // pair index in [0, halfL)
    if (p >= halfL) return;

    // Phase 1: 6 x 8B index loads (each covers two adjacent rows).
    const int2 sa = __ldg(f0 + p), da = __ldg(t0 + p);
    const int2 sb = __ldg(f1 + p), db = __ldg(t1 + p);
    const int2 sc = __ldg(f2 + p), dc = __ldg(t2 + p);

    // Phase 2: 6 independent 16B gathers in flight.
    float4 v0 = __ldg(m0 + (size_t)sa.x * D4 + q);
    float4 v1 = __ldg(m0 + (size_t)sa.y * D4 + q);
    float4 v2 = __ldg(m1 + (size_t)sb.x * D4 + q);
    float4 v3 = __ldg(m1 + (size_t)sb.y * D4 + q);
    float4 v4 = __ldg(m2 + (size_t)sc.x * D4 + q);
    float4 v5 = __ldg(m2 + (size_t)sc.y * D4 + q);

    // Phase 3: scatters (write-once, full-line coalesced per 16-thread group).
    out[(size_t)da.x * D4 + q] = v0;
    out[(size_t)da.y * D4 + q] = v1;
    out[(size_t)db.x * D4 + q] = v2;
    out[(size_t)db.y * D4 + q] = v3;
    out[(size_t)dc.x * D4 + q] = v4;
    out[(size_t)dc.y * D4 + q] = v5;
}

// Generic fallback (used only if L is odd): one thread per row-float4.
__global__ void __launch_bounds__(256)
mis_generic_kernel(const float4* __restrict__ m0,
                   const float4* __restrict__ m1,
                   const float4* __restrict__ m2,
                   const int*    __restrict__ f0,
                   const int*    __restrict__ f1,
                   const int*    __restrict__ f2,
                   const int*    __restrict__ t0,
                   const int*    __restrict__ t1,
                   const int*    __restrict__ t2,
                   float4*       __restrict__ out,
                   int L)
{
    int tid = blockIdx.x * blockDim.x + threadIdx.x;
    int row = tid >> 4;
    int q   = tid & (D4 - 1);
    if (row >= 3 * L) return;
    const float4* m; const int* f; const int* t; int r;
    if (row < L)          { m = m0; f = f0; t = t0; r = row;         }
    else if (row < 2 * L) { m = m1; f = f1; t = t1; r = row - L;     }
    else                  { m = m2; f = f2; t = t2; r = row - 2 * L; }
    int src = __ldg(f + r);
    int dst = __ldg(t + r);
    out[(size_t)dst * D4 + q] = __ldg(m + (size_t)src * D4 + q);
}

extern "C" void kernel_launch(void* const* d_in, const int* in_sizes, int n_in,
                              void* d_out, int out_size)
{
    const float4* m0 = (const float4*)d_in[0];
    const float4* m1 = (const float4*)d_in[1];
    const float4* m2 = (const float4*)d_in[2];
    float4* out = (float4*)d_out;

    const int L     = in_sizes[3];     // length of from0
    const int block = 256;

    if ((L & 1) == 0) {
        const int halfL = L >> 1;
        const long long threads = (long long)halfL * D4;
        const int grid = (int)((threads + block - 1) / block);
        mis_u6p_kernel<<<grid, block>>>(m0, m1, m2,
                                        (const int2*)d_in[3],
                                        (const int2*)d_in[4],
                                        (const int2*)d_in[5],
                                        (const int2*)d_in[6],
                                        (const int2*)d_in[7],
                                        (const int2*)d_in[8],
                                        out, halfL);
    } else {
        const long long threads = (long long)3 * L * D4;
        const int grid = (int)((threads + block - 1) / block);
        mis_generic_kernel<<<grid, block>>>(m0, m1, m2,
                                            (const int*)d_in[3],
                                            (const int*)d_in[4],
                                            (const int*)d_in[5],
                                            (const int*)d_in[6],
                                            (const int*)d_in[7],
                                            (const int*)d_in[8],
                                            out, L);
    }
}